// round 13
// baseline (speedup 1.0000x reference)
#include <cuda_runtime.h>
#include <cuda_bf16.h>
#include <math_constants.h>
#include <cstdint>

// VectorQuantizer (per-dimension scalar codebooks), SINGLE self-contained kernel.
// Each block: sorts its OWN 4 codebook dims in smem (redundantly per b-chunk,
// warp-local bitonic => ~3 block barriers), builds midpoints, then does
// 4 interleaved lower_bound searches per thread. No cross-block dependencies
// except the final deterministic loss reduction.
//   z: [B, D] f32 (B=2048, D=128); codebooks: [D, K] f32 (K=512)

#define VQ_D 128
#define VQ_K 512
#define VQ_THREADS 256
#define NDIMS 4
#define PADIDX(i) ((i) + ((i) >> 5))
#define PADK (VQ_K + (VQ_K >> 5))            // 528

__device__ float        g_partials[1024];
__device__ unsigned int g_count = 0;

__global__ void __launch_bounds__(VQ_THREADS)
vq_kernel(const float4* __restrict__ z4,
          const float4* __restrict__ cb4,
          float* __restrict__ qout,      // may be null
          float* __restrict__ loss_out,  // may be null
          int nb, float inv_n, int vec_ok)
{
    __shared__ float ss  [NDIMS][VQ_K];    // sorted codes (sort scratch)
    __shared__ float smid[NDIMS][PADK];    // padded midpoints
    __shared__ float swred[VQ_THREADS / 32];
    __shared__ float sblock;
    __shared__ int   s_is_last;

    const int dg   = blockIdx.x;           // dim group 0..31
    const int d0   = dg * NDIMS;
    const int tid  = threadIdx.x;
    const int lane = tid & 31;
    const int wid  = tid >> 5;

    // ---- prefetch z (hides under the sort) ----
    const int b = blockIdx.y * VQ_THREADS + tid;
    const bool v = (b < nb);
    float4 zv = v ? z4[b * (VQ_D / 4) + dg] : make_float4(0.f, 0.f, 0.f, 0.f);

    // ---- load 4 codebook rows (coalesced float4; 512 float4, 2/thread) ----
#pragma unroll
    for (int i = tid; i < NDIMS * (VQ_K / 4); i += VQ_THREADS) {
        int di = i >> 7;
        int e4 = i & 127;
        float4 c = cb4[(d0 + di) * (VQ_K / 4) + e4];
        ss[di][e4 * 4 + 0] = c.x;
        ss[di][e4 * 4 + 1] = c.y;
        ss[di][e4 * 4 + 2] = c.z;
        ss[di][e4 * 4 + 3] = c.w;
    }
    __syncthreads();

    // ---- bitonic sort: 4 dims in parallel, warp w -> dim (w>>1), half (w&1) ----
    // j<=128 stages: pairs stay inside the warp's 256-span -> __syncwarp only.
    // j==256 (k=512): block-wide exchange -> __syncthreads.
    const int wdim  = wid >> 1;
    const int wbase = (wid & 1) * 256;

    for (int k = 2; k <= VQ_K; k <<= 1) {
        for (int j = k >> 1; j >= 1; j >>= 1) {
            if (j == 256) {
                __syncthreads();
                // 1024 pairs total (256 per dim), 4 per thread
#pragma unroll
                for (int t = 0; t < 4; t++) {
                    int p  = tid + t * VQ_THREADS;   // [0,1024)
                    int di = p >> 8;
                    int i  = p & 255;                // partner i|256
                    float a = ss[di][i], c = ss[di][i | 256];
                    // k=512: (i & 512)==0 always -> ascending
                    if (a > c) { ss[di][i] = c; ss[di][i | 256] = a; }
                }
                __syncthreads();
            } else {
                __syncwarp();
#pragma unroll
                for (int t = 0; t < 4; t++) {
                    int p  = t * 32 + lane;                           // [0,128)
                    int il = ((p & ~(j - 1)) << 1) | (p & (j - 1));   // bit j == 0
                    int i  = wbase + il;
                    int ix = i | j;
                    float a = ss[wdim][i], c = ss[wdim][ix];
                    bool up = ((i & k) == 0);
                    if ((a > c) == up) { ss[wdim][i] = c; ss[wdim][ix] = a; }
                }
            }
        }
    }
    __syncthreads();

    // ---- build padded Voronoi midpoints ----
#pragma unroll
    for (int i = tid; i < NDIMS * VQ_K; i += VQ_THREADS) {
        int di = i >> 9;
        int e  = i & (VQ_K - 1);
        float c  = ss[di][e];
        float cn = (e < VQ_K - 1) ? ss[di][e + 1] : 0.0f;
        smid[di][PADIDX(e)] = (e < VQ_K - 1) ? 0.5f * (c + cn) : CUDART_INF_F;
    }
    __syncthreads();

    // ---- 4 interleaved lower_bound searches (ILP hides LDS latency) ----
    int p0 = 0, p1 = 0, p2 = 0, p3 = 0;
#pragma unroll
    for (int step = VQ_K / 2; step >= 1; step >>= 1) {
        if (smid[0][PADIDX(p0 + step - 1)] < zv.x) p0 += step;
        if (smid[1][PADIDX(p1 + step - 1)] < zv.y) p1 += step;
        if (smid[2][PADIDX(p2 + step - 1)] < zv.z) p2 += step;
        if (smid[3][PADIDX(p3 + step - 1)] < zv.w) p3 += step;
    }
    // code gather straight from smem (no global round-trip)
    float q0 = ss[0][p0];
    float q1 = ss[1][p1];
    float q2 = ss[2][p2];
    float q3 = ss[3][p3];

    float acc = 0.0f;
    if (v) {
        float e0 = q0 - zv.x, e1 = q1 - zv.y, e2 = q2 - zv.z, e3 = q3 - zv.w;
        acc = e0 * e0 + e1 * e1 + e2 * e2 + e3 * e3;
        if (qout) {
            float o0 = zv.x + (q0 - zv.x);
            float o1 = zv.y + (q1 - zv.y);
            float o2 = zv.z + (q2 - zv.z);
            float o3 = zv.w + (q3 - zv.w);
            if (vec_ok) {
                reinterpret_cast<float4*>(qout)[b * (VQ_D / 4) + dg] =
                    make_float4(o0, o1, o2, o3);
            } else {
                float* qp = qout + b * VQ_D + d0;
                qp[0] = o0; qp[1] = o1; qp[2] = o2; qp[3] = o3;
            }
        }
    }

    // ---- block loss reduction (deterministic) ----
#pragma unroll
    for (int o = 16; o > 0; o >>= 1)
        acc += __shfl_down_sync(0xffffffffu, acc, o);
    if (lane == 0) swred[wid] = acc;
    __syncthreads();
    if (tid == 0) {
        float t = 0.0f;
#pragma unroll
        for (int ww = 0; ww < VQ_THREADS / 32; ww++) t += swred[ww];
        sblock = t;
    }
    __syncthreads();

    // ---- cross-block finalize (last block, deterministic order) ----
    const int nblocks = gridDim.x * gridDim.y;
    const int bindex  = blockIdx.y * gridDim.x + blockIdx.x;
    if (tid == 0) {
        g_partials[bindex] = sblock;
        __threadfence();
        unsigned int c = atomicAdd(&g_count, 1u);
        s_is_last = (c == (unsigned int)(nblocks - 1));
    }
    __syncthreads();

    if (s_is_last && tid < 32) {
        __threadfence();
        float t = 0.0f;
        for (int i = lane; i < nblocks; i += 32)
            t += g_partials[i];
#pragma unroll
        for (int o = 16; o > 0; o >>= 1)
            t += __shfl_down_sync(0xffffffffu, t, o);
        if (lane == 0) {
            if (loss_out) *loss_out = t * inv_n;
            g_count = 0;   // reset for next graph replay
        }
    }
}

extern "C" void kernel_launch(void* const* d_in, const int* in_sizes, int n_in,
                              void* d_out, int out_size)
{
    const float* z  = (const float*)d_in[0];   // [B, D]
    const float* cb = (const float*)d_in[1];   // [D, K]
    float* out = (float*)d_out;

    const int nb       = in_sizes[0] / VQ_D;   // B
    const int bd_total = nb * VQ_D;

    float* loss_ptr = nullptr;
    float* q_ptr    = nullptr;
    if (out_size == bd_total + 1)      { loss_ptr = out; q_ptr = out + 1; }
    else if (out_size == bd_total)     { q_ptr = out; }
    else if (out_size == 1)            { loss_ptr = out; }
    else                               { q_ptr = out; }

    int chunks = (nb + VQ_THREADS - 1) / VQ_THREADS;   // 8 for B=2048
    if (chunks > 32) chunks = 32;                      // g_partials bound

    float inv_n = 1.0f / (float)bd_total;
    int vec_ok = (q_ptr != nullptr) && ((((std::uintptr_t)q_ptr) & 15) == 0);

    dim3 grid(VQ_D / NDIMS, chunks);               // (32, 8) = 256 blocks
    vq_kernel<<<grid, VQ_THREADS>>>(
        (const float4*)z, (const float4*)cb, q_ptr, loss_ptr, nb, inv_n, vec_ok);
}

// round 14
// speedup vs baseline: 1.6658x; 1.6658x over previous
#include <cuda_runtime.h>
#include <cuda_bf16.h>
#include <math_constants.h>
#include <cstdint>

// VectorQuantizer (per-dimension scalar codebooks), two-phase (R10 structure):
//   K1: per-dim hybrid bitonic sort (warp shuffles; smem only for j>=64)
//       -> global sorted codes + Voronoi midpoints
//   K2: 4-dim-grouped lower_bound; top-3 levels on register pivots (SEL trees),
//       bottom-6 on padded smem; code gather from L2
//   z: [B, D] f32 (B=2048, D=128); codebooks: [D, K] f32 (K=512)

#define VQ_D 128
#define VQ_K 512
#define VQ_THREADS 256
#define NDIMS 4
#define PADIDX(i) ((i) + ((i) >> 5))
#define PADK (VQ_K + (VQ_K >> 5))            // 528

__device__ float        g_code[VQ_D * VQ_K];
__device__ float4       g_mid4[VQ_D * VQ_K / 4];
__device__ float        g_partials[1024];
__device__ unsigned int g_count = 0;

// compare-exchange across lanes: element x at global index i, partner i^j (j<=16)
__device__ __forceinline__ float cmpx(float x, int i, int j, int k)
{
    float y = __shfl_xor_sync(0xffffffffu, x, j);
    bool keepmin = (((i & j) == 0) == ((i & k) == 0));
    return keepmin ? fminf(x, y) : fmaxf(x, y);
}

// ---------------- Kernel 1: hybrid bitonic sort + midpoints ----------------
__global__ void __launch_bounds__(VQ_THREADS)
vq_sort_kernel(const float* __restrict__ cb)
{
    __shared__ float s[VQ_K];
    const int d    = blockIdx.x;
    const int tid  = threadIdx.x;
    const int l    = tid & 31;
    const int w    = tid >> 5;
    const int base = w * 64;

    float a = cb[d * VQ_K + base + l];
    float b = cb[d * VQ_K + base + 32 + l];

#pragma unroll
    for (int k = 2; k <= 32; k <<= 1) {
#pragma unroll
        for (int j = k >> 1; j >= 1; j >>= 1) {
            a = cmpx(a, base + l,      j, k);
            b = cmpx(b, base + 32 + l, j, k);
        }
    }
    {
        bool up = ((base & 64) == 0);
        if ((a > b) == up) { float t = a; a = b; b = t; }
#pragma unroll
        for (int j = 16; j >= 1; j >>= 1) {
            a = cmpx(a, base + l,      j, 64);
            b = cmpx(b, base + 32 + l, j, 64);
        }
    }
    s[base + l]      = a;
    s[base + 32 + l] = b;

    for (int k = 128; k <= VQ_K; k <<= 1) {
        for (int j = k >> 1; j >= 64; j >>= 1) {
            __syncthreads();
#pragma unroll
            for (int t = 0; t < VQ_K / VQ_THREADS; t++) {
                int i   = tid + t * VQ_THREADS;
                int ixj = i ^ j;
                if (ixj > i) {
                    float x = s[i], y = s[ixj];
                    bool up = ((i & k) == 0);
                    if ((x > y) == up) { s[i] = y; s[ixj] = x; }
                }
            }
        }
        __syncthreads();
        a = s[base + l];
        b = s[base + 32 + l];
        bool up = ((base & k) == 0);
        if ((a > b) == up) { float t = a; a = b; b = t; }
#pragma unroll
        for (int j = 16; j >= 1; j >>= 1) {
            a = cmpx(a, base + l,      j, k);
            b = cmpx(b, base + 32 + l, j, k);
        }
        s[base + l]      = a;
        s[base + 32 + l] = b;
    }
    __syncthreads();

    float* gm = reinterpret_cast<float*>(g_mid4);
#pragma unroll
    for (int t = 0; t < VQ_K / VQ_THREADS; t++) {
        int i = tid + t * VQ_THREADS;
        float c  = s[i];
        float cn = (i < VQ_K - 1) ? s[i + 1] : 0.0f;
        g_code[d * VQ_K + i] = c;
        gm[d * VQ_K + i] = (i < VQ_K - 1) ? 0.5f * (c + cn) : CUDART_INF_F;
    }
}

// ---------------- Kernel 2: search (reg pivots + smem) + loss ----------------
__global__ void __launch_bounds__(VQ_THREADS)
vq_search_kernel(const float4* __restrict__ z4,
                 float* __restrict__ qout,      // may be null
                 float* __restrict__ loss_out,  // may be null
                 int nb, float inv_n, int vec_ok)
{
    __shared__ float smid[NDIMS][PADK];
    __shared__ float swred[VQ_THREADS / 32];
    __shared__ float sblock;
    __shared__ int   s_is_last;

    const int dg   = blockIdx.x;          // dim group 0..31
    const int d0   = dg * NDIMS;
    const int tid  = threadIdx.x;
    const int lane = tid & 31;
    const int wid  = tid >> 5;

    // prefetch z (one float4 = 4 dims for one b)
    const int b = blockIdx.y * VQ_THREADS + tid;
    const bool v = (b < nb);
    float4 zv = v ? z4[b * (VQ_D / 4) + dg] : make_float4(0.f, 0.f, 0.f, 0.f);

    // stage 4 dims' midpoints (padded): 512 float4 loads, 2 per thread
#pragma unroll
    for (int i = tid; i < NDIMS * (VQ_K / 4); i += VQ_THREADS) {
        int di = i >> 7;
        int e4 = i & 127;
        int e  = e4 * 4;
        float4 m = g_mid4[(d0 + di) * (VQ_K / 4) + e4];
        smid[di][PADIDX(e + 0)] = m.x;
        smid[di][PADIDX(e + 1)] = m.y;
        smid[di][PADIDX(e + 2)] = m.z;
        smid[di][PADIDX(e + 3)] = m.w;
    }
    __syncthreads();

    // register pivots per dim (broadcast LDS, conflict-free):
    // level 256: [255]; level 128: [127],[383]; level 64: [63],[191],[319],[447]
    float P1[NDIMS], P2a[NDIMS], P2b[NDIMS];
    float P3a[NDIMS], P3b[NDIMS], P3c[NDIMS], P3d[NDIMS];
#pragma unroll
    for (int di = 0; di < NDIMS; di++) {
        P1 [di] = smid[di][PADIDX(255)];
        P2a[di] = smid[di][PADIDX(127)];
        P2b[di] = smid[di][PADIDX(383)];
        P3a[di] = smid[di][PADIDX(63)];
        P3b[di] = smid[di][PADIDX(191)];
        P3c[di] = smid[di][PADIDX(319)];
        P3d[di] = smid[di][PADIDX(447)];
    }

    const float zr[NDIMS] = { zv.x, zv.y, zv.z, zv.w };
    int pos[NDIMS];
    // top-3 levels on registers (SEL trees, no LDS)
#pragma unroll
    for (int di = 0; di < NDIMS; di++) {
        bool c0 = P1[di] < zr[di];
        float t1 = c0 ? P2b[di] : P2a[di];
        bool c1 = t1 < zr[di];
        float t2 = c0 ? (c1 ? P3d[di] : P3c[di]) : (c1 ? P3b[di] : P3a[di]);
        bool c2 = t2 < zr[di];
        pos[di] = (c0 ? 256 : 0) + (c1 ? 128 : 0) + (c2 ? 64 : 0);
    }
    // bottom-6 levels on padded smem, 4 chains interleaved (ILP)
#pragma unroll
    for (int step = 32; step >= 1; step >>= 1) {
#pragma unroll
        for (int di = 0; di < NDIMS; di++)
            if (smid[di][PADIDX(pos[di] + step - 1)] < zr[di]) pos[di] += step;
    }
    // final code gather from L2-hot global (independent loads)
    float q0 = __ldg(&g_code[(d0 + 0) * VQ_K + pos[0]]);
    float q1 = __ldg(&g_code[(d0 + 1) * VQ_K + pos[1]]);
    float q2 = __ldg(&g_code[(d0 + 2) * VQ_K + pos[2]]);
    float q3 = __ldg(&g_code[(d0 + 3) * VQ_K + pos[3]]);

    float acc = 0.0f;
    if (v) {
        float e0 = q0 - zv.x, e1 = q1 - zv.y, e2 = q2 - zv.z, e3 = q3 - zv.w;
        acc = e0 * e0 + e1 * e1 + e2 * e2 + e3 * e3;
        if (qout) {
            float o0 = zv.x + (q0 - zv.x);
            float o1 = zv.y + (q1 - zv.y);
            float o2 = zv.z + (q2 - zv.z);
            float o3 = zv.w + (q3 - zv.w);
            if (vec_ok) {
                reinterpret_cast<float4*>(qout)[b * (VQ_D / 4) + dg] =
                    make_float4(o0, o1, o2, o3);
            } else {
                float* qp = qout + b * VQ_D + d0;
                qp[0] = o0; qp[1] = o1; qp[2] = o2; qp[3] = o3;
            }
        }
    }

    // block loss reduction (deterministic)
#pragma unroll
    for (int o = 16; o > 0; o >>= 1)
        acc += __shfl_down_sync(0xffffffffu, acc, o);
    if (lane == 0) swred[wid] = acc;
    __syncthreads();
    if (tid == 0) {
        float t = 0.0f;
#pragma unroll
        for (int ww = 0; ww < VQ_THREADS / 32; ww++) t += swred[ww];
        sblock = t;
    }
    __syncthreads();

    // cross-block finalize (last block, deterministic order)
    const int nblocks = gridDim.x * gridDim.y;
    const int bindex  = blockIdx.y * gridDim.x + blockIdx.x;
    if (tid == 0) {
        g_partials[bindex] = sblock;
        __threadfence();
        unsigned int c = atomicAdd(&g_count, 1u);
        s_is_last = (c == (unsigned int)(nblocks - 1));
    }
    __syncthreads();

    if (s_is_last && tid < 32) {
        __threadfence();
        float t = 0.0f;
        for (int i = lane; i < nblocks; i += 32)
            t += g_partials[i];
#pragma unroll
        for (int o = 16; o > 0; o >>= 1)
            t += __shfl_down_sync(0xffffffffu, t, o);
        if (lane == 0) {
            if (loss_out) *loss_out = t * inv_n;
            g_count = 0;   // reset for next graph replay
        }
    }
}

extern "C" void kernel_launch(void* const* d_in, const int* in_sizes, int n_in,
                              void* d_out, int out_size)
{
    const float* z  = (const float*)d_in[0];   // [B, D]
    const float* cb = (const float*)d_in[1];   // [D, K]
    float* out = (float*)d_out;

    const int nb       = in_sizes[0] / VQ_D;   // B
    const int bd_total = nb * VQ_D;

    float* loss_ptr = nullptr;
    float* q_ptr    = nullptr;
    if (out_size == bd_total + 1)      { loss_ptr = out; q_ptr = out + 1; }
    else if (out_size == bd_total)     { q_ptr = out; }
    else if (out_size == 1)            { loss_ptr = out; }
    else                               { q_ptr = out; }

    int chunks = (nb + VQ_THREADS - 1) / VQ_THREADS;   // 8 for B=2048
    if (chunks > 32) chunks = 32;                      // g_partials bound

    float inv_n = 1.0f / (float)bd_total;
    int vec_ok = (q_ptr != nullptr) && ((((std::uintptr_t)q_ptr) & 15) == 0);

    vq_sort_kernel<<<VQ_D, VQ_THREADS>>>(cb);
    dim3 grid(VQ_D / NDIMS, chunks);               // (32, 8) = 256 blocks
    vq_search_kernel<<<grid, VQ_THREADS>>>(
        (const float4*)z, q_ptr, loss_ptr, nb, inv_n, vec_ok);
}

// round 15
// speedup vs baseline: 1.6917x; 1.0155x over previous
#include <cuda_runtime.h>
#include <cuda_bf16.h>
#include <math_constants.h>
#include <cstdint>

// VectorQuantizer (per-dimension scalar codebooks), two-phase:
//   K1: per-dim hybrid bitonic sort (warp shuffles; smem only for j>=64)
//       -> global sorted codes + Voronoi midpoints
//   K2: 4-dim-grouped lower_bound, BPT=2 (8 interleaved chains/thread),
//       grid = 128 blocks = ONE wave on 148 SMs; code gather from L2
//   z: [B, D] f32 (B=2048, D=128); codebooks: [D, K] f32 (K=512)

#define VQ_D 128
#define VQ_K 512
#define VQ_THREADS 256
#define NDIMS 4
#define VQ_BPT 2                             // batch elems per thread
#define CHUNK_B (VQ_THREADS * VQ_BPT)        // 512
#define PADIDX(i) ((i) + ((i) >> 5))
#define PADK (VQ_K + (VQ_K >> 5))            // 528

__device__ float        g_code[VQ_D * VQ_K];
__device__ float4       g_mid4[VQ_D * VQ_K / 4];
__device__ float        g_partials[1024];
__device__ unsigned int g_count = 0;

// compare-exchange across lanes: element x at global index i, partner i^j (j<=16)
__device__ __forceinline__ float cmpx(float x, int i, int j, int k)
{
    float y = __shfl_xor_sync(0xffffffffu, x, j);
    bool keepmin = (((i & j) == 0) == ((i & k) == 0));
    return keepmin ? fminf(x, y) : fmaxf(x, y);
}

// ---------------- Kernel 1: hybrid bitonic sort + midpoints ----------------
__global__ void __launch_bounds__(VQ_THREADS)
vq_sort_kernel(const float* __restrict__ cb)
{
    __shared__ float s[VQ_K];
    const int d    = blockIdx.x;
    const int tid  = threadIdx.x;
    const int l    = tid & 31;
    const int w    = tid >> 5;
    const int base = w * 64;

    float a = cb[d * VQ_K + base + l];
    float b = cb[d * VQ_K + base + 32 + l];

#pragma unroll
    for (int k = 2; k <= 32; k <<= 1) {
#pragma unroll
        for (int j = k >> 1; j >= 1; j >>= 1) {
            a = cmpx(a, base + l,      j, k);
            b = cmpx(b, base + 32 + l, j, k);
        }
    }
    {
        bool up = ((base & 64) == 0);
        if ((a > b) == up) { float t = a; a = b; b = t; }
#pragma unroll
        for (int j = 16; j >= 1; j >>= 1) {
            a = cmpx(a, base + l,      j, 64);
            b = cmpx(b, base + 32 + l, j, 64);
        }
    }
    s[base + l]      = a;
    s[base + 32 + l] = b;

    for (int k = 128; k <= VQ_K; k <<= 1) {
        for (int j = k >> 1; j >= 64; j >>= 1) {
            __syncthreads();
#pragma unroll
            for (int t = 0; t < VQ_K / VQ_THREADS; t++) {
                int i   = tid + t * VQ_THREADS;
                int ixj = i ^ j;
                if (ixj > i) {
                    float x = s[i], y = s[ixj];
                    bool up = ((i & k) == 0);
                    if ((x > y) == up) { s[i] = y; s[ixj] = x; }
                }
            }
        }
        __syncthreads();
        a = s[base + l];
        b = s[base + 32 + l];
        bool up = ((base & k) == 0);
        if ((a > b) == up) { float t = a; a = b; b = t; }
#pragma unroll
        for (int j = 16; j >= 1; j >>= 1) {
            a = cmpx(a, base + l,      j, k);
            b = cmpx(b, base + 32 + l, j, k);
        }
        s[base + l]      = a;
        s[base + 32 + l] = b;
    }
    __syncthreads();

    float* gm = reinterpret_cast<float*>(g_mid4);
#pragma unroll
    for (int t = 0; t < VQ_K / VQ_THREADS; t++) {
        int i = tid + t * VQ_THREADS;
        float c  = s[i];
        float cn = (i < VQ_K - 1) ? s[i + 1] : 0.0f;
        g_code[d * VQ_K + i] = c;
        gm[d * VQ_K + i] = (i < VQ_K - 1) ? 0.5f * (c + cn) : CUDART_INF_F;
    }
}

// ---------------- Kernel 2: BPT=2 search (one wave) + loss ----------------
__global__ void __launch_bounds__(VQ_THREADS)
vq_search_kernel(const float4* __restrict__ z4,
                 float* __restrict__ qout,      // may be null
                 float* __restrict__ loss_out,  // may be null
                 int nb, float inv_n, int vec_ok)
{
    __shared__ float smid[NDIMS][PADK];
    __shared__ float swred[VQ_THREADS / 32];
    __shared__ float sblock;
    __shared__ int   s_is_last;

    const int dg   = blockIdx.x;          // dim group 0..31
    const int d0   = dg * NDIMS;
    const int tid  = threadIdx.x;
    const int lane = tid & 31;
    const int wid  = tid >> 5;

    // prefetch z for two batch elements (hidden under staging)
    const int b0 = blockIdx.y * CHUNK_B + tid;
    const int b1 = b0 + VQ_THREADS;
    const bool v0 = (b0 < nb), v1 = (b1 < nb);
    float4 zv0 = v0 ? z4[b0 * (VQ_D / 4) + dg] : make_float4(0.f, 0.f, 0.f, 0.f);
    float4 zv1 = v1 ? z4[b1 * (VQ_D / 4) + dg] : make_float4(0.f, 0.f, 0.f, 0.f);

    // stage 4 dims' midpoints (padded): 512 float4 loads, 2 per thread
#pragma unroll
    for (int i = tid; i < NDIMS * (VQ_K / 4); i += VQ_THREADS) {
        int di = i >> 7;
        int e4 = i & 127;
        int e  = e4 * 4;
        float4 m = g_mid4[(d0 + di) * (VQ_K / 4) + e4];
        smid[di][PADIDX(e + 0)] = m.x;
        smid[di][PADIDX(e + 1)] = m.y;
        smid[di][PADIDX(e + 2)] = m.z;
        smid[di][PADIDX(e + 3)] = m.w;
    }
    __syncthreads();

    // 8 interleaved lower_bound searches (2 batch elems x 4 dims)
    const float zr[8] = { zv0.x, zv0.y, zv0.z, zv0.w,
                          zv1.x, zv1.y, zv1.z, zv1.w };
    int p[8];
#pragma unroll
    for (int c = 0; c < 8; c++) p[c] = 0;
#pragma unroll
    for (int step = VQ_K / 2; step >= 1; step >>= 1) {
#pragma unroll
        for (int c = 0; c < 8; c++)
            if (smid[c & 3][PADIDX(p[c] + step - 1)] < zr[c]) p[c] += step;
    }
    // final code gather from L2-hot global (8 independent loads)
    float q[8];
#pragma unroll
    for (int c = 0; c < 8; c++)
        q[c] = __ldg(&g_code[(d0 + (c & 3)) * VQ_K + p[c]]);

    float acc = 0.0f;
    if (v0) {
        float e0 = q[0] - zr[0], e1 = q[1] - zr[1];
        float e2 = q[2] - zr[2], e3 = q[3] - zr[3];
        acc += e0 * e0 + e1 * e1 + e2 * e2 + e3 * e3;
        if (qout) {
            float o0 = zr[0] + (q[0] - zr[0]);
            float o1 = zr[1] + (q[1] - zr[1]);
            float o2 = zr[2] + (q[2] - zr[2]);
            float o3 = zr[3] + (q[3] - zr[3]);
            if (vec_ok) {
                reinterpret_cast<float4*>(qout)[b0 * (VQ_D / 4) + dg] =
                    make_float4(o0, o1, o2, o3);
            } else {
                float* qp = qout + b0 * VQ_D + d0;
                qp[0] = o0; qp[1] = o1; qp[2] = o2; qp[3] = o3;
            }
        }
    }
    if (v1) {
        float e4 = q[4] - zr[4], e5 = q[5] - zr[5];
        float e6 = q[6] - zr[6], e7 = q[7] - zr[7];
        acc += e4 * e4 + e5 * e5 + e6 * e6 + e7 * e7;
        if (qout) {
            float o4 = zr[4] + (q[4] - zr[4]);
            float o5 = zr[5] + (q[5] - zr[5]);
            float o6 = zr[6] + (q[6] - zr[6]);
            float o7 = zr[7] + (q[7] - zr[7]);
            if (vec_ok) {
                reinterpret_cast<float4*>(qout)[b1 * (VQ_D / 4) + dg] =
                    make_float4(o4, o5, o6, o7);
            } else {
                float* qp = qout + b1 * VQ_D + d0;
                qp[0] = o4; qp[1] = o5; qp[2] = o6; qp[3] = o7;
            }
        }
    }

    // block loss reduction (deterministic)
#pragma unroll
    for (int o = 16; o > 0; o >>= 1)
        acc += __shfl_down_sync(0xffffffffu, acc, o);
    if (lane == 0) swred[wid] = acc;
    __syncthreads();
    if (tid == 0) {
        float t = 0.0f;
#pragma unroll
        for (int ww = 0; ww < VQ_THREADS / 32; ww++) t += swred[ww];
        sblock = t;
    }
    __syncthreads();

    // cross-block finalize (last block, deterministic order)
    const int nblocks = gridDim.x * gridDim.y;
    const int bindex  = blockIdx.y * gridDim.x + blockIdx.x;
    if (tid == 0) {
        g_partials[bindex] = sblock;
        __threadfence();
        unsigned int c = atomicAdd(&g_count, 1u);
        s_is_last = (c == (unsigned int)(nblocks - 1));
    }
    __syncthreads();

    if (s_is_last && tid < 32) {
        __threadfence();
        float t = 0.0f;
        for (int i = lane; i < nblocks; i += 32)
            t += g_partials[i];
#pragma unroll
        for (int o = 16; o > 0; o >>= 1)
            t += __shfl_down_sync(0xffffffffu, t, o);
        if (lane == 0) {
            if (loss_out) *loss_out = t * inv_n;
            g_count = 0;   // reset for next graph replay
        }
    }
}

extern "C" void kernel_launch(void* const* d_in, const int* in_sizes, int n_in,
                              void* d_out, int out_size)
{
    const float* z  = (const float*)d_in[0];   // [B, D]
    const float* cb = (const float*)d_in[1];   // [D, K]
    float* out = (float*)d_out;

    const int nb       = in_sizes[0] / VQ_D;   // B
    const int bd_total = nb * VQ_D;

    float* loss_ptr = nullptr;
    float* q_ptr    = nullptr;
    if (out_size == bd_total + 1)      { loss_ptr = out; q_ptr = out + 1; }
    else if (out_size == bd_total)     { q_ptr = out; }
    else if (out_size == 1)            { loss_ptr = out; }
    else                               { q_ptr = out; }

    int chunks = (nb + CHUNK_B - 1) / CHUNK_B;     // 4 for B=2048
    if (chunks > 32) chunks = 32;                  // g_partials bound

    float inv_n = 1.0f / (float)bd_total;
    int vec_ok = (q_ptr != nullptr) && ((((std::uintptr_t)q_ptr) & 15) == 0);

    vq_sort_kernel<<<VQ_D, VQ_THREADS>>>(cb);
    dim3 grid(VQ_D / NDIMS, chunks);               // (32, 4) = 128 blocks: 1 wave
    vq_search_kernel<<<grid, VQ_THREADS>>>(
        (const float4*)z, q_ptr, loss_ptr, nb, inv_n, vec_ok);
}